// round 2
// baseline (speedup 1.0000x reference)
#include <cuda_runtime.h>
#include <math.h>

#define N_NODES 50000
#define N_EDGES 800000
#define ET (N_EDGES + N_NODES)   // edges + self loops
#define IN_F 128
#define HEADS 4
#define HC 128                   // HEADS * OUT_F
#define NEG 0.2f
#define NODE_TILE 8

// Scratch (allocation-free rule: __device__ globals)
__device__ float g_xl[(size_t)N_NODES * HC];
__device__ float g_xr[(size_t)N_NODES * HC];
__device__ float g_logits[(size_t)ET * HEADS];
__device__ float g_m[(size_t)N_NODES * HEADS];
__device__ float g_denom[(size_t)N_NODES * HEADS];

__device__ __forceinline__ void atomicMaxF(float* addr, float val) {
    if (val >= 0.0f)
        atomicMax((int*)addr, __float_as_int(val));
    else
        atomicMin((unsigned int*)addr, __float_as_uint(val));
}

// ---------------------------------------------------------------------------
// K0: init out = bias (broadcast), m = -inf, denom = 0
// ---------------------------------------------------------------------------
__global__ void k_init(const float* __restrict__ bias, float* __restrict__ out) {
    int i = blockIdx.x * blockDim.x + threadIdx.x;
    if (i < N_NODES * HC) out[i] = bias[i & (HC - 1)];
    if (i < N_NODES * HEADS) {
        g_m[i] = -INFINITY;
        g_denom[i] = 0.0f;
    }
}

// ---------------------------------------------------------------------------
// K1: xl = x @ W_l, xr = x @ W_r   (fp32, register-tiled over 8 nodes)
// block: 128 threads = one output column each; grid: N_NODES/8 blocks
// ---------------------------------------------------------------------------
__global__ void k_proj(const float* __restrict__ x,
                       const float* __restrict__ Wl,
                       const float* __restrict__ Wr) {
    __shared__ float xs[NODE_TILE][IN_F];
    const int j = threadIdx.x;               // output column 0..127
    const int n0 = blockIdx.x * NODE_TILE;

#pragma unroll
    for (int n = 0; n < NODE_TILE; n++)
        xs[n][j] = x[(size_t)(n0 + n) * IN_F + j];
    __syncthreads();

    float accl[NODE_TILE], accr[NODE_TILE];
#pragma unroll
    for (int n = 0; n < NODE_TILE; n++) { accl[n] = 0.0f; accr[n] = 0.0f; }

#pragma unroll 4
    for (int k = 0; k < IN_F; k++) {
        const float wl = Wl[k * HC + j];
        const float wr = Wr[k * HC + j];
#pragma unroll
        for (int n = 0; n < NODE_TILE; n++) {
            accl[n] = fmaf(xs[n][k], wl, accl[n]);
            accr[n] = fmaf(xs[n][k], wr, accr[n]);
        }
    }

#pragma unroll
    for (int n = 0; n < NODE_TILE; n++) {
        g_xl[(size_t)(n0 + n) * HC + j] = accl[n];
        g_xr[(size_t)(n0 + n) * HC + j] = accr[n];
    }
}

// ---------------------------------------------------------------------------
// K2: per-edge attention logits + segment max  (one warp per edge)
// logit[e,h] = sum_c leaky_relu(xl[src,h,c] + xr[dst,h,c]) * att[h,c]
// ---------------------------------------------------------------------------
__global__ void k_logits(const int* __restrict__ ei,
                         const float* __restrict__ att) {
    const int warp = (blockIdx.x * blockDim.x + threadIdx.x) >> 5;
    const int lane = threadIdx.x & 31;
    if (warp >= ET) return;

    int src, dst;
    if (warp < N_EDGES) {
        src = ei[warp];
        dst = ei[N_EDGES + warp];
    } else {
        src = dst = warp - N_EDGES;
    }

    const float* xl = g_xl + (size_t)src * HC;
    const float* xr = g_xr + (size_t)dst * HC;

    float s[HEADS];
#pragma unroll
    for (int h = 0; h < HEADS; h++) {
        float v = xl[h * 32 + lane] + xr[h * 32 + lane];
        v = (v > 0.0f) ? v : NEG * v;
        s[h] = v * att[h * 32 + lane];
    }
#pragma unroll
    for (int off = 16; off; off >>= 1) {
#pragma unroll
        for (int h = 0; h < HEADS; h++)
            s[h] += __shfl_xor_sync(0xffffffffu, s[h], off);
    }
    if (lane == 0) {
#pragma unroll
        for (int h = 0; h < HEADS; h++) {
            g_logits[(size_t)warp * HEADS + h] = s[h];
            atomicMaxF(&g_m[dst * HEADS + h], s[h]);
        }
    }
}

// ---------------------------------------------------------------------------
// K3: ex = exp(logit - m[dst]); denom[dst] += ex  (thread per edge-head)
// overwrites g_logits with ex
// ---------------------------------------------------------------------------
__global__ void k_exp(const int* __restrict__ ei) {
    const long long t = (long long)blockIdx.x * blockDim.x + threadIdx.x;
    if (t >= (long long)ET * HEADS) return;
    const int e = (int)(t >> 2);
    const int h = (int)(t & 3);
    const int dst = (e < N_EDGES) ? ei[N_EDGES + e] : e - N_EDGES;
    const float ex = __expf(g_logits[t] - g_m[dst * HEADS + h]);
    g_logits[t] = ex;
    atomicAdd(&g_denom[dst * HEADS + h], ex);
}

// ---------------------------------------------------------------------------
// K4: out[dst] += xl[src] * alpha   (one warp per edge, atomic scatter)
// ---------------------------------------------------------------------------
__global__ void k_scatter(const int* __restrict__ ei,
                          float* __restrict__ out) {
    const int warp = (blockIdx.x * blockDim.x + threadIdx.x) >> 5;
    const int lane = threadIdx.x & 31;
    if (warp >= ET) return;

    int src, dst;
    if (warp < N_EDGES) {
        src = ei[warp];
        dst = ei[N_EDGES + warp];
    } else {
        src = dst = warp - N_EDGES;
    }

    float alpha[HEADS];
#pragma unroll
    for (int h = 0; h < HEADS; h++) {
        const float ex = g_logits[(size_t)warp * HEADS + h];
        alpha[h] = ex / (g_denom[dst * HEADS + h] + 1e-16f);
    }

    const float* xl = g_xl + (size_t)src * HC;
    float* op = out + (size_t)dst * HC;
#pragma unroll
    for (int h = 0; h < HEADS; h++) {
        const float v = xl[h * 32 + lane] * alpha[h];
        atomicAdd(&op[h * 32 + lane], v);
    }
}

// ---------------------------------------------------------------------------
extern "C" void kernel_launch(void* const* d_in, const int* in_sizes, int n_in,
                              void* d_out, int out_size) {
    const float* x    = (const float*)d_in[0];
    const int*   ei   = (const int*)d_in[1];
    const float* Wl   = (const float*)d_in[2];
    const float* Wr   = (const float*)d_in[3];
    const float* att  = (const float*)d_in[4];
    const float* bias = (const float*)d_in[5];
    float*       out  = (float*)d_out;

    (void)in_sizes; (void)n_in; (void)out_size;

    // K0: init output with bias, init softmax accumulators
    k_init<<<(N_NODES * HC + 255) / 256, 256>>>(bias, out);

    // K1: node projections
    k_proj<<<N_NODES / NODE_TILE, IN_F>>>(x, Wl, Wr);

    // K2: edge logits + segment max (warp per edge)
    {
        long long threads = (long long)ET * 32;
        k_logits<<<(unsigned)((threads + 255) / 256), 256>>>(ei, att);
    }

    // K3: exp + denom
    {
        long long threads = (long long)ET * HEADS;
        k_exp<<<(unsigned)((threads + 255) / 256), 256>>>(ei);
    }

    // K4: weighted scatter aggregate (warp per edge)
    {
        long long threads = (long long)ET * 32;
        k_scatter<<<(unsigned)((threads + 255) / 256), 256>>>(ei, out);
    }
}

// round 3
// speedup vs baseline: 1.3952x; 1.3952x over previous
#include <cuda_runtime.h>
#include <math.h>

#define N_NODES 50000
#define N_EDGES 800000
#define ET (N_EDGES + N_NODES)   // edges + self loops
#define IN_F 128
#define HEADS 4
#define HC 128                   // HEADS * OUT_F
#define NEG 0.2f
#define NODE_TILE 16

// Scratch (allocation-free rule: __device__ globals)
__device__ float g_xl[(size_t)N_NODES * HC];
__device__ float g_xr[(size_t)N_NODES * HC];
__device__ int   g_deg[N_NODES];
__device__ int   g_off[N_NODES];
__device__ int   g_cur[N_NODES];
__device__ int   g_csr[ET];       // src node per CSR slot (dst implicit)

// ---------------------------------------------------------------------------
// K_a: zero degree/cursor arrays
// ---------------------------------------------------------------------------
__global__ void k_zero() {
    int i = blockIdx.x * blockDim.x + threadIdx.x;
    if (i < N_NODES) { g_deg[i] = 0; g_cur[i] = 0; }
}

// ---------------------------------------------------------------------------
// K_b: count in-degree per dst (self loops included)
// ---------------------------------------------------------------------------
__global__ void k_count(const int* __restrict__ ei) {
    int e = blockIdx.x * blockDim.x + threadIdx.x;
    if (e >= ET) return;
    int dst = (e < N_EDGES) ? ei[N_EDGES + e] : e - N_EDGES;
    atomicAdd(&g_deg[dst], 1);
}

// ---------------------------------------------------------------------------
// K_c: exclusive prefix sum of g_deg -> g_off (single block)
// ---------------------------------------------------------------------------
__global__ void k_scan() {
    const int T = 1024;
    const int C = (N_NODES + T - 1) / T;   // 49
    __shared__ int part[T];
    int t = threadIdx.x;
    int base = t * C;
    int s = 0;
    for (int i = 0; i < C; i++) {
        int idx = base + i;
        if (idx < N_NODES) s += g_deg[idx];
    }
    part[t] = s;
    __syncthreads();
    // inclusive Hillis-Steele scan
    for (int off = 1; off < T; off <<= 1) {
        int v = (t >= off) ? part[t - off] : 0;
        __syncthreads();
        part[t] += v;
        __syncthreads();
    }
    int run = (t == 0) ? 0 : part[t - 1];
    for (int i = 0; i < C; i++) {
        int idx = base + i;
        if (idx < N_NODES) { g_off[idx] = run; run += g_deg[idx]; }
    }
}

// ---------------------------------------------------------------------------
// K_d: fill CSR (src per slot)
// ---------------------------------------------------------------------------
__global__ void k_fill(const int* __restrict__ ei) {
    int e = blockIdx.x * blockDim.x + threadIdx.x;
    if (e >= ET) return;
    int src, dst;
    if (e < N_EDGES) { src = ei[e]; dst = ei[N_EDGES + e]; }
    else             { src = dst = e - N_EDGES; }
    int pos = g_off[dst] + atomicAdd(&g_cur[dst], 1);
    g_csr[pos] = src;
}

// ---------------------------------------------------------------------------
// K1: xl = x @ W_l, xr = x @ W_r   (fp32, register-tiled over 16 nodes)
// ---------------------------------------------------------------------------
__global__ void k_proj(const float* __restrict__ x,
                       const float* __restrict__ Wl,
                       const float* __restrict__ Wr) {
    __shared__ float xs[NODE_TILE][IN_F];
    const int j = threadIdx.x;               // output column 0..127
    const int n0 = blockIdx.x * NODE_TILE;

#pragma unroll
    for (int n = 0; n < NODE_TILE; n++)
        xs[n][j] = x[(size_t)(n0 + n) * IN_F + j];
    __syncthreads();

    float accl[NODE_TILE], accr[NODE_TILE];
#pragma unroll
    for (int n = 0; n < NODE_TILE; n++) { accl[n] = 0.0f; accr[n] = 0.0f; }

#pragma unroll 4
    for (int k = 0; k < IN_F; k++) {
        const float wl = Wl[k * HC + j];
        const float wr = Wr[k * HC + j];
#pragma unroll
        for (int n = 0; n < NODE_TILE; n++) {
            accl[n] = fmaf(xs[n][k], wl, accl[n]);
            accr[n] = fmaf(xs[n][k], wr, accr[n]);
        }
    }

#pragma unroll
    for (int n = 0; n < NODE_TILE; n++) {
        g_xl[(size_t)(n0 + n) * HC + j] = accl[n];
        g_xr[(size_t)(n0 + n) * HC + j] = accr[n];
    }
}

// ---------------------------------------------------------------------------
// K2: fused online-softmax aggregation. One warp per destination node.
//   For each incoming edge: gather xl[src] (once), compute GATv2 logit,
//   update running (m, d, acc) per head, finally out = acc/(d+1e-16) + bias.
// ---------------------------------------------------------------------------
__global__ void k_fused(const float* __restrict__ att,
                        const float* __restrict__ bias,
                        float* __restrict__ out) {
    const int w = (blockIdx.x * blockDim.x + threadIdx.x) >> 5;  // node id
    const int lane = threadIdx.x & 31;
    if (w >= N_NODES) return;

    const int beg = g_off[w];
    const int deg = g_deg[w];

    float xrv[HEADS], atv[HEADS];
#pragma unroll
    for (int h = 0; h < HEADS; h++) {
        xrv[h] = g_xr[(size_t)w * HC + h * 32 + lane];
        atv[h] = att[h * 32 + lane];
    }

    float m[HEADS], d[HEADS], acc[HEADS];
#pragma unroll
    for (int h = 0; h < HEADS; h++) { m[h] = -INFINITY; d[h] = 0.0f; acc[h] = 0.0f; }

    for (int i = 0; i < deg; i++) {
        const int src = g_csr[beg + i];
        const float* xlp = g_xl + (size_t)src * HC;

        float xlv[HEADS], s[HEADS];
#pragma unroll
        for (int h = 0; h < HEADS; h++) {
            xlv[h] = xlp[h * 32 + lane];
            float v = xlv[h] + xrv[h];
            v = (v > 0.0f) ? v : NEG * v;
            s[h] = v * atv[h];
        }
        // warp reduce logits (result replicated to all lanes)
#pragma unroll
        for (int off = 16; off; off >>= 1) {
#pragma unroll
            for (int h = 0; h < HEADS; h++)
                s[h] += __shfl_xor_sync(0xffffffffu, s[h], off);
        }
        // online softmax update (branch is warp-uniform: s,m replicated)
#pragma unroll
        for (int h = 0; h < HEADS; h++) {
            if (s[h] > m[h]) {
                const float sc = __expf(m[h] - s[h]);   // 0 on first edge
                d[h] = fmaf(d[h], sc, 1.0f);
                acc[h] = fmaf(acc[h], sc, xlv[h]);
                m[h] = s[h];
            } else {
                const float p = __expf(s[h] - m[h]);
                d[h] += p;
                acc[h] = fmaf(p, xlv[h], acc[h]);
            }
        }
    }

#pragma unroll
    for (int h = 0; h < HEADS; h++) {
        out[(size_t)w * HC + h * 32 + lane] =
            acc[h] / (d[h] + 1e-16f) + bias[h * 32 + lane];
    }
}

// ---------------------------------------------------------------------------
extern "C" void kernel_launch(void* const* d_in, const int* in_sizes, int n_in,
                              void* d_out, int out_size) {
    const float* x    = (const float*)d_in[0];
    const int*   ei   = (const int*)d_in[1];
    const float* Wl   = (const float*)d_in[2];
    const float* Wr   = (const float*)d_in[3];
    const float* att  = (const float*)d_in[4];
    const float* bias = (const float*)d_in[5];
    float*       out  = (float*)d_out;

    (void)in_sizes; (void)n_in; (void)out_size;

    // CSR build
    k_zero<<<(N_NODES + 255) / 256, 256>>>();
    k_count<<<(ET + 255) / 256, 256>>>(ei);
    k_scan<<<1, 1024>>>();
    k_fill<<<(ET + 255) / 256, 256>>>(ei);

    // node projections
    k_proj<<<N_NODES / NODE_TILE, IN_F>>>(x, Wl, Wr);

    // fused logits + online segment-softmax + aggregation (warp per node)
    k_fused<<<(N_NODES * 32 + 255) / 256, 256>>>(att, bias, out);
}

// round 4
// speedup vs baseline: 1.8245x; 1.3077x over previous
#include <cuda_runtime.h>
#include <math.h>

#define N_NODES 50000
#define N_EDGES 800000
#define ET (N_EDGES + N_NODES)   // edges + self loops
#define IN_F 128
#define HEADS 4
#define HC 128                   // HEADS * OUT_F
#define NEG 0.2f
#define NT 16                    // nodes per proj block
#define NT2 (NT / 2)

// Scratch (allocation-free rule: __device__ globals)
__device__ float g_xl[(size_t)N_NODES * HC];
__device__ float g_xr[(size_t)N_NODES * HC];
__device__ int   g_deg[N_NODES];
__device__ int   g_off[N_NODES];
__device__ int   g_cur[N_NODES];
__device__ int   g_csr[ET];       // src node per CSR slot (dst implicit)

// ---------------------------------------------------------------------------
// packed f32x2 helpers
// ---------------------------------------------------------------------------
__device__ __forceinline__ unsigned long long ffma2(unsigned long long a,
                                                    unsigned long long b,
                                                    unsigned long long c) {
    unsigned long long d;
    asm("fma.rn.f32x2 %0, %1, %2, %3;" : "=l"(d) : "l"(a), "l"(b), "l"(c));
    return d;
}
__device__ __forceinline__ unsigned long long pack2(float lo, float hi) {
    unsigned long long r;
    asm("mov.b64 %0, {%1, %2};" : "=l"(r) : "f"(lo), "f"(hi));
    return r;
}
__device__ __forceinline__ float2 unpack2(unsigned long long v) {
    float lo, hi;
    asm("mov.b64 {%0, %1}, %2;" : "=f"(lo), "=f"(hi) : "l"(v));
    return make_float2(lo, hi);
}

// ---------------------------------------------------------------------------
// K_a: zero degree/cursor arrays
// ---------------------------------------------------------------------------
__global__ void k_zero() {
    int i = blockIdx.x * blockDim.x + threadIdx.x;
    if (i < N_NODES) { g_deg[i] = 0; g_cur[i] = 0; }
}

// ---------------------------------------------------------------------------
// K_b: count in-degree per dst (self loops included)
// ---------------------------------------------------------------------------
__global__ void k_count(const int* __restrict__ ei) {
    int e = blockIdx.x * blockDim.x + threadIdx.x;
    if (e >= ET) return;
    int dst = (e < N_EDGES) ? ei[N_EDGES + e] : e - N_EDGES;
    atomicAdd(&g_deg[dst], 1);
}

// ---------------------------------------------------------------------------
// K_c: exclusive prefix sum of g_deg -> g_off (single block)
// ---------------------------------------------------------------------------
__global__ void k_scan() {
    const int T = 1024;
    const int C = (N_NODES + T - 1) / T;
    __shared__ int part[T];
    int t = threadIdx.x;
    int base = t * C;
    int s = 0;
    for (int i = 0; i < C; i++) {
        int idx = base + i;
        if (idx < N_NODES) s += g_deg[idx];
    }
    part[t] = s;
    __syncthreads();
    for (int off = 1; off < T; off <<= 1) {
        int v = (t >= off) ? part[t - off] : 0;
        __syncthreads();
        part[t] += v;
        __syncthreads();
    }
    int run = (t == 0) ? 0 : part[t - 1];
    for (int i = 0; i < C; i++) {
        int idx = base + i;
        if (idx < N_NODES) { g_off[idx] = run; run += g_deg[idx]; }
    }
}

// ---------------------------------------------------------------------------
// K_d: fill CSR (src per slot)
// ---------------------------------------------------------------------------
__global__ void k_fill(const int* __restrict__ ei) {
    int e = blockIdx.x * blockDim.x + threadIdx.x;
    if (e >= ET) return;
    int src, dst;
    if (e < N_EDGES) { src = ei[e]; dst = ei[N_EDGES + e]; }
    else             { src = dst = e - N_EDGES; }
    int pos = g_off[dst] + atomicAdd(&g_cur[dst], 1);
    g_csr[pos] = src;
}

// ---------------------------------------------------------------------------
// K1: xl = x @ W_l, xr = x @ W_r   via packed FFMA2 over node pairs.
// 128 threads = one output column each; NT=16 nodes per block (8 f32x2 pairs).
// ---------------------------------------------------------------------------
__global__ void k_proj(const float* __restrict__ x,
                       const float* __restrict__ Wl,
                       const float* __restrict__ Wr) {
    __shared__ float2 xs2[IN_F][NT2 + 1];   // [feature][node-pair], padded
    const int j = threadIdx.x;              // output column 0..127 (= feature row too)
    const int n0 = blockIdx.x * NT;

    // load + transpose: thread j owns feature j of all 16 nodes
#pragma unroll
    for (int p = 0; p < NT2; p++) {
        float a = x[(size_t)(n0 + 2 * p)     * IN_F + j];
        float b = x[(size_t)(n0 + 2 * p + 1) * IN_F + j];
        xs2[j][p] = make_float2(a, b);
    }
    __syncthreads();

    unsigned long long accl[NT2], accr[NT2];
#pragma unroll
    for (int p = 0; p < NT2; p++) { accl[p] = 0ull; accr[p] = 0ull; }

#pragma unroll 4
    for (int k = 0; k < IN_F; k++) {
        const float wl = Wl[k * HC + j];
        const float wr = Wr[k * HC + j];
        const unsigned long long wl2 = pack2(wl, wl);
        const unsigned long long wr2 = pack2(wr, wr);
#pragma unroll
        for (int p = 0; p < NT2; p++) {
            const unsigned long long xv =
                *reinterpret_cast<const unsigned long long*>(&xs2[k][p]);
            accl[p] = ffma2(xv, wl2, accl[p]);
            accr[p] = ffma2(xv, wr2, accr[p]);
        }
    }

#pragma unroll
    for (int p = 0; p < NT2; p++) {
        const float2 al = unpack2(accl[p]);
        const float2 ar = unpack2(accr[p]);
        g_xl[(size_t)(n0 + 2 * p)     * HC + j] = al.x;
        g_xl[(size_t)(n0 + 2 * p + 1) * HC + j] = al.y;
        g_xr[(size_t)(n0 + 2 * p)     * HC + j] = ar.x;
        g_xr[(size_t)(n0 + 2 * p + 1) * HC + j] = ar.y;
    }
}

// ---------------------------------------------------------------------------
// K2: fused online-softmax aggregation. One warp per destination node.
// Lane l owns channels 4l..4l+3 (one float4); head = l>>3 lives in one
// 8-lane group -> logit reduction = 3 butterfly shuffles.
// ---------------------------------------------------------------------------
__global__ void k_fused(const float* __restrict__ att,
                        const float* __restrict__ bias,
                        float* __restrict__ out) {
    const int w = (blockIdx.x * blockDim.x + threadIdx.x) >> 5;  // node id
    const int lane = threadIdx.x & 31;
    if (w >= N_NODES) return;

    const int beg = g_off[w];
    const int deg = g_deg[w];
    const int c4 = lane * 4;

    const float4 xr4 = *reinterpret_cast<const float4*>(g_xr + (size_t)w * HC + c4);
    const float4 at4 = *reinterpret_cast<const float4*>(att + c4);

    float m = -INFINITY, d = 0.0f;
    float4 acc = make_float4(0.f, 0.f, 0.f, 0.f);

    for (int base = 0; base < deg; base += 32) {
        const int idx = base + lane;
        const int src_l = (idx < deg) ? g_csr[beg + idx] : 0;
        int n = deg - base; if (n > 32) n = 32;

        for (int j = 0; j < n; j++) {
            const int src = __shfl_sync(0xffffffffu, src_l, j);
            const float4 xl4 =
                *reinterpret_cast<const float4*>(g_xl + (size_t)src * HC + c4);

            float v0 = xl4.x + xr4.x;
            float v1 = xl4.y + xr4.y;
            float v2 = xl4.z + xr4.z;
            float v3 = xl4.w + xr4.w;
            v0 = (v0 > 0.f) ? v0 : NEG * v0;
            v1 = (v1 > 0.f) ? v1 : NEG * v1;
            v2 = (v2 > 0.f) ? v2 : NEG * v2;
            v3 = (v3 > 0.f) ? v3 : NEG * v3;
            float t = v0 * at4.x;
            t = fmaf(v1, at4.y, t);
            t = fmaf(v2, at4.z, t);
            t = fmaf(v3, at4.w, t);

            // reduce within the 8-lane head group (replicates result)
            t += __shfl_xor_sync(0xffffffffu, t, 1);
            t += __shfl_xor_sync(0xffffffffu, t, 2);
            t += __shfl_xor_sync(0xffffffffu, t, 4);

            // branchless online softmax update
            const float mn = fmaxf(m, t);
            const float sc = __expf(m - mn);   // 1 if m unchanged, 0 on first edge
            const float p  = __expf(t - mn);
            d = fmaf(d, sc, p);
            acc.x = fmaf(acc.x, sc, p * xl4.x);
            acc.y = fmaf(acc.y, sc, p * xl4.y);
            acc.z = fmaf(acc.z, sc, p * xl4.z);
            acc.w = fmaf(acc.w, sc, p * xl4.w);
            m = mn;
        }
    }

    const float inv = 1.0f / (d + 1e-16f);
    const float4 b4 = *reinterpret_cast<const float4*>(bias + c4);
    float4 o;
    o.x = fmaf(acc.x, inv, b4.x);
    o.y = fmaf(acc.y, inv, b4.y);
    o.z = fmaf(acc.z, inv, b4.z);
    o.w = fmaf(acc.w, inv, b4.w);
    *reinterpret_cast<float4*>(out + (size_t)w * HC + c4) = o;
}

// ---------------------------------------------------------------------------
extern "C" void kernel_launch(void* const* d_in, const int* in_sizes, int n_in,
                              void* d_out, int out_size) {
    const float* x    = (const float*)d_in[0];
    const int*   ei   = (const int*)d_in[1];
    const float* Wl   = (const float*)d_in[2];
    const float* Wr   = (const float*)d_in[3];
    const float* att  = (const float*)d_in[4];
    const float* bias = (const float*)d_in[5];
    float*       out  = (float*)d_out;

    (void)in_sizes; (void)n_in; (void)out_size;

    // CSR build
    k_zero<<<(N_NODES + 255) / 256, 256>>>();
    k_count<<<(ET + 255) / 256, 256>>>(ei);
    k_scan<<<1, 1024>>>();
    k_fill<<<(ET + 255) / 256, 256>>>(ei);

    // node projections (FFMA2)
    k_proj<<<N_NODES / NT, IN_F>>>(x, Wl, Wr);

    // fused logits + online segment-softmax + aggregation (warp per node)
    k_fused<<<(N_NODES * 32 + 255) / 256, 256>>>(att, bias, out);
}